// round 1
// baseline (speedup 1.0000x reference)
#include <cuda_runtime.h>

// DIN HistAttentionSeqPoolingLayer, folded layer-1 formulation.
// B=4096, T=200, E=64, H1=80, H2=40.
// out[b][e] = sum_{t<len_b} score(b,t) * keys[b][t][e]
// score = Wd . sigmoid(b2 + W2^T sigmoid(b1 + W1^T [q,k,q-k,q*k])) + bd
// Fold: pre1_h = c_h + sum_e k_e * V[h][e],
//   c_h = b1_h + sum_e q_e*(W1a+W1c)_{eh}
//   V[h][e] = (W1b - W1c)_{eh} + q_e * W1d_{eh}

#define BB 4096
#define TT 200
#define EE 64
#define HH1 80
#define HH2 40
#define NTHREADS 224   // 7 warps; thread == t
#define NWARPS 7

__global__ __launch_bounds__(NTHREADS, 2)
void din_pool_kernel(const float* __restrict__ query,
                     const float* __restrict__ keys,
                     const int*   __restrict__ keys_length,
                     const float* __restrict__ W1,
                     const float* __restrict__ b1,
                     const float* __restrict__ W2,
                     const float* __restrict__ b2,
                     const float* __restrict__ Wd,
                     const float* __restrict__ bd,
                     float* __restrict__ out)
{
    __shared__ float q_sm[EE];
    __shared__ float c_sm[HH1];
    __shared__ float V_sm[HH1][EE];      // 20 KB, rows 16B-aligned
    __shared__ float W2_sm[HH1][HH2];    // 12.5 KB
    __shared__ float Wd_sm[HH2];
    __shared__ float b2_sm[HH2];
    __shared__ float part[NWARPS][EE];   // per-warp output partials

    const int b   = blockIdx.x;
    const int tid = threadIdx.x;
    const int len = keys_length[b];

    // ---- stage q, W2, Wd, b2 ----
    if (tid < EE) q_sm[tid] = query[b * EE + tid];
    for (int i = tid; i < HH1 * HH2; i += NTHREADS)
        (&W2_sm[0][0])[i] = W2[i];
    if (tid < HH2) { Wd_sm[tid] = Wd[tid]; b2_sm[tid] = b2[tid]; }
    __syncthreads();

    // ---- per-batch folded layer-1 weights V[h][e] and bias c[h] ----
    for (int idx = tid; idx < HH1 * EE; idx += NTHREADS) {
        int h = idx >> 6;
        int e = idx & 63;
        float Bv = W1[(64  + e) * HH1 + h];
        float Cv = W1[(128 + e) * HH1 + h];
        float Dv = W1[(192 + e) * HH1 + h];
        V_sm[h][e] = Bv - Cv + q_sm[e] * Dv;
    }
    for (int h = tid; h < HH1; h += NTHREADS) {
        float s = b1[h];
        #pragma unroll 8
        for (int e = 0; e < EE; e++)
            s += q_sm[e] * (W1[e * HH1 + h] + W1[(128 + e) * HH1 + h]);
        c_sm[h] = s;
    }
    __syncthreads();

    const int t    = tid;
    const int warp = tid >> 5;
    const int lane = tid & 31;
    const bool haveT = (t < TT);
    const bool warpActive = (warp * 32) < len;

    // ---- per-thread key vector in registers ----
    float ka[EE];
    if (haveT) {
        const float4* kp = reinterpret_cast<const float4*>(
            keys + ((long)b * TT + t) * EE);
        #pragma unroll
        for (int i = 0; i < 16; i++)
            reinterpret_cast<float4*>(ka)[i] = kp[i];
    } else {
        #pragma unroll
        for (int i = 0; i < EE; i++) ka[i] = 0.f;
    }

    float score = 0.f;
    if (warpActive && haveT) {
        // layer-2 accumulators, init with b2
        float4 acc2[10];
        #pragma unroll
        for (int j = 0; j < 10; j++)
            acc2[j] = make_float4(b2_sm[4*j], b2_sm[4*j+1],
                                  b2_sm[4*j+2], b2_sm[4*j+3]);

        #pragma unroll 2
        for (int h = 0; h < HH1; h++) {
            const float4* vr = reinterpret_cast<const float4*>(V_sm[h]);
            float s0 = 0.f, s1 = 0.f, s2 = 0.f, s3 = 0.f;
            #pragma unroll
            for (int i = 0; i < 16; i++) {
                float4 v = vr[i];            // uniform broadcast LDS.128
                s0 += ka[4*i+0] * v.x;
                s1 += ka[4*i+1] * v.y;
                s2 += ka[4*i+2] * v.z;
                s3 += ka[4*i+3] * v.w;
            }
            float pre = c_sm[h] + ((s0 + s1) + (s2 + s3));
            float h1  = 1.f / (1.f + __expf(-pre));

            const float4* w2r = reinterpret_cast<const float4*>(W2_sm[h]);
            #pragma unroll
            for (int j = 0; j < 10; j++) {
                float4 w = w2r[j];           // uniform broadcast LDS.128
                acc2[j].x += h1 * w.x;
                acc2[j].y += h1 * w.y;
                acc2[j].z += h1 * w.z;
                acc2[j].w += h1 * w.w;
            }
        }

        float sc = bd[0];
        #pragma unroll
        for (int j = 0; j < 10; j++) {
            sc += Wd_sm[4*j+0] * (1.f / (1.f + __expf(-acc2[j].x)));
            sc += Wd_sm[4*j+1] * (1.f / (1.f + __expf(-acc2[j].y)));
            sc += Wd_sm[4*j+2] * (1.f / (1.f + __expf(-acc2[j].z)));
            sc += Wd_sm[4*j+3] * (1.f / (1.f + __expf(-acc2[j].w)));
        }
        score = (t < len) ? sc : 0.f;
    }

    // ---- pooled output: warp butterfly reduce per e, cross-warp via smem ----
    #pragma unroll
    for (int e = 0; e < EE; e++) {
        float v = score * ka[e];             // score==0 for masked / oob t
        v += __shfl_xor_sync(0xFFFFFFFFu, v, 16);
        v += __shfl_xor_sync(0xFFFFFFFFu, v, 8);
        v += __shfl_xor_sync(0xFFFFFFFFu, v, 4);
        v += __shfl_xor_sync(0xFFFFFFFFu, v, 2);
        v += __shfl_xor_sync(0xFFFFFFFFu, v, 1);
        if (lane == 0) part[warp][e] = v;
    }
    __syncthreads();

    if (tid < EE) {
        float s = 0.f;
        #pragma unroll
        for (int w = 0; w < NWARPS; w++) s += part[w][tid];
        out[b * EE + tid] = s;
    }
}

extern "C" void kernel_launch(void* const* d_in, const int* in_sizes, int n_in,
                              void* d_out, int out_size) {
    const float* query       = (const float*)d_in[0];
    const float* keys        = (const float*)d_in[1];
    const int*   keys_length = (const int*)  d_in[2];
    const float* W1          = (const float*)d_in[3];
    const float* b1          = (const float*)d_in[4];
    const float* W2          = (const float*)d_in[5];
    const float* b2          = (const float*)d_in[6];
    const float* Wd          = (const float*)d_in[7];
    const float* bd          = (const float*)d_in[8];
    float* out = (float*)d_out;

    din_pool_kernel<<<BB, NTHREADS>>>(query, keys, keys_length,
                                      W1, b1, W2, b2, Wd, bd, out);
}

// round 3
// speedup vs baseline: 1.1184x; 1.1184x over previous
#include <cuda_runtime.h>

// DIN HistAttentionSeqPoolingLayer — SMEM-staged, folded layer-1, len-bounded.
// B=4096, T=200, E=64, H1=80, H2=40.
// out[b][e] = sum_{t<len_b} score(b,t) * keys[b][t][e]
// Fold: pre1_h = c_h + sum_e k_e * V[h][e]
//   c_h = b1_h + sum_e q_e*(W1a+W1c)_{eh}
//   V[h][e] = (W1b - W1c)_{eh} + q_e * W1d_{eh}

#define BB 4096
#define TT 200
#define EE 64
#define HH1 80
#define HH2 40
#define NTHREADS 224
#define KPAD 68            // K row stride in smem: 68 mod 32 = 4 -> conflict-free LDS.128

// smem layout (floats)
#define OFF_K    0                       // 200*68 = 13600
#define OFF_V    (OFF_K + TT*KPAD)       // 80*64  = 5120
#define OFF_W2   (OFF_V + HH1*EE)        // 80*40  = 3200
#define OFF_Q    (OFF_W2 + HH1*HH2)      // 64
#define OFF_C    (OFF_Q + EE)            // 80
#define OFF_WD   (OFF_C + HH1)           // 40
#define OFF_B2   (OFF_WD + HH2)          // 40
#define OFF_SC   (OFF_B2 + HH2)          // 200
#define OFF_PART (OFF_SC + TT)           // 192
#define SMEM_FLOATS (OFF_PART + 3*EE)
#define SMEM_BYTES  (SMEM_FLOATS * 4)

__global__ __launch_bounds__(NTHREADS, 2)
void din_pool_kernel(const float* __restrict__ query,
                     const float* __restrict__ keys,
                     const int*   __restrict__ keys_length,
                     const float* __restrict__ W1,
                     const float* __restrict__ b1,
                     const float* __restrict__ W2,
                     const float* __restrict__ b2,
                     const float* __restrict__ Wd,
                     const float* __restrict__ bd,
                     float* __restrict__ out)
{
    extern __shared__ float sm[];
    float* Ksm  = sm + OFF_K;
    float* Vsm  = sm + OFF_V;
    float* W2sm = sm + OFF_W2;
    float* qsm  = sm + OFF_Q;
    float* csm  = sm + OFF_C;
    float* Wdsm = sm + OFF_WD;
    float* b2sm = sm + OFF_B2;
    float* scsm = sm + OFF_SC;
    float* part = sm + OFF_PART;

    const int b   = blockIdx.x;
    const int tid = threadIdx.x;
    const int len = keys_length[b];

    // ---- stage q, W2, Wd, b2 + coalesced K staging (only rows < len) ----
    if (tid < EE) qsm[tid] = query[b * EE + tid];
    if (tid < HH2) { Wdsm[tid] = Wd[tid]; b2sm[tid] = b2[tid]; }
    for (int i = tid; i < (HH1 * HH2) / 4; i += NTHREADS)
        reinterpret_cast<float4*>(W2sm)[i] =
            reinterpret_cast<const float4*>(W2)[i];

    // keys[b]: rows [0,len) = len*16 float4, coalesced; scatter into padded rows.
    // Rows >= len are left unstaged: MLP results for t>=len are overwritten to 0
    // and pooling never reads them.
    {
        const float4* kg = reinterpret_cast<const float4*>(keys + (long)b * TT * EE);
        const int n4 = len * (EE / 4);
        for (int i = tid; i < n4; i += NTHREADS) {
            int t = i >> 4;          // 16 float4 per row
            int j = i & 15;
            float4 v = kg[i];
            *reinterpret_cast<float4*>(Ksm + t * KPAD + j * 4) = v;
        }
    }
    __syncthreads();

    // ---- folded per-batch layer-1: V[h][e], c[h] ----
    for (int idx = tid; idx < HH1 * EE; idx += NTHREADS) {
        int h = idx >> 6;
        int e = idx & 63;
        float Bv = W1[(64  + e) * HH1 + h];
        float Cv = W1[(128 + e) * HH1 + h];
        float Dv = W1[(192 + e) * HH1 + h];
        Vsm[h * EE + e] = Bv - Cv + qsm[e] * Dv;
    }
    for (int h = tid; h < HH1; h += NTHREADS) {
        float s = b1[h];
        #pragma unroll 8
        for (int e = 0; e < EE; e++)
            s += qsm[e] * (W1[e * HH1 + h] + W1[(128 + e) * HH1 + h]);
        csm[h] = s;
    }
    __syncthreads();

    // ---- per-thread-t MLP; K read from smem (conflict-free) ----
    const int t    = tid;
    const int warp = tid >> 5;
    const bool active = (t < TT) && ((warp << 5) < len);

    float sc = 0.f;
    if (active) {
        const float4* kr = reinterpret_cast<const float4*>(Ksm + t * KPAD);

        float4 a2[HH2 / 4];
        #pragma unroll
        for (int j = 0; j < HH2 / 4; j++)
            a2[j] = reinterpret_cast<const float4*>(b2sm)[j];

        #pragma unroll 2
        for (int h = 0; h < HH1; h++) {
            const float4* vr = reinterpret_cast<const float4*>(Vsm + h * EE);
            float s0 = csm[h], s1 = 0.f, s2 = 0.f, s3 = 0.f;
            #pragma unroll
            for (int i = 0; i < EE / 4; i++) {
                float4 k4 = kr[i];       // per-lane, conflict-free (17-perm)
                float4 v4 = vr[i];       // uniform broadcast
                s0 += k4.x * v4.x;
                s1 += k4.y * v4.y;
                s2 += k4.z * v4.z;
                s3 += k4.w * v4.w;
            }
            float pre = (s0 + s1) + (s2 + s3);
            float h1  = 1.f / (1.f + __expf(-pre));

            const float4* wr = reinterpret_cast<const float4*>(W2sm + h * HH2);
            #pragma unroll
            for (int j = 0; j < HH2 / 4; j++) {
                float4 w = wr[j];        // uniform broadcast
                a2[j].x += h1 * w.x;
                a2[j].y += h1 * w.y;
                a2[j].z += h1 * w.z;
                a2[j].w += h1 * w.w;
            }
        }

        sc = bd[0];
        #pragma unroll
        for (int j = 0; j < HH2 / 4; j++) {
            sc += Wdsm[4*j+0] * (1.f / (1.f + __expf(-a2[j].x)));
            sc += Wdsm[4*j+1] * (1.f / (1.f + __expf(-a2[j].y)));
            sc += Wdsm[4*j+2] * (1.f / (1.f + __expf(-a2[j].z)));
            sc += Wdsm[4*j+3] * (1.f / (1.f + __expf(-a2[j].w)));
        }
        if (t >= len) sc = 0.f;          // discard garbage from unstaged rows
    }
    if (t < TT) scsm[t] = sc;
    __syncthreads();

    // ---- pooling: out[e] = sum_{t<len} sc[t] * K[t][e]  (3 t-groups x 64 e) ----
    if (tid < 3 * EE) {
        const int g = tid >> 6;          // uniform per warp (64 | warp boundaries)
        const int e = tid & 63;
        float acc = 0.f;
        for (int tt = g; tt < len; tt += 3)
            acc += scsm[tt] * Ksm[tt * KPAD + e];   // sc broadcast; K conflict-free
        part[tid] = acc;
    }
    __syncthreads();

    if (tid < EE)
        out[b * EE + tid] = part[tid] + part[EE + tid] + part[2 * EE + tid];
}

extern "C" void kernel_launch(void* const* d_in, const int* in_sizes, int n_in,
                              void* d_out, int out_size) {
    const float* query       = (const float*)d_in[0];
    const float* keys        = (const float*)d_in[1];
    const int*   keys_length = (const int*)  d_in[2];
    const float* W1          = (const float*)d_in[3];
    const float* b1          = (const float*)d_in[4];
    const float* W2          = (const float*)d_in[5];
    const float* b2          = (const float*)d_in[6];
    const float* Wd          = (const float*)d_in[7];
    const float* bd          = (const float*)d_in[8];
    float* out = (float*)d_out;

    // opt-in to >48KB dynamic smem (host-side attribute set; idempotent,
    // executes immediately — not a captured stream op)
    cudaFuncSetAttribute(din_pool_kernel,
                         cudaFuncAttributeMaxDynamicSharedMemorySize, SMEM_BYTES);

    din_pool_kernel<<<BB, NTHREADS, SMEM_BYTES>>>(query, keys, keys_length,
                                                  W1, b1, W2, b2, Wd, bd, out);
}